// round 6
// baseline (speedup 1.0000x reference)
#include <cuda_runtime.h>
#include <cuda_bf16.h>
#include <cuda_fp16.h>
#include <math.h>

#define D 128
#define NMAX 50048
#define EMAX 1310720
#define SLOPE 0.01f

// ---------------- static device scratch ----------------
// zeroed-per-launch region: [0,NMAX)=deg(f32), [NMAX,2N)=cnt(i32), [2N,3N)=cur(i32)
__device__ unsigned int g_zero3[3 * NMAX];
__device__ float g_dg[NMAX];
__device__ float g_dinv[NMAX];
__device__ int   g_ptr[NMAX + 1];
__device__ int   g_bsum[1024];
__device__ uint4 g_edges[EMAX];      // {col, wG, wS, pad}; node segments padded to x4
__device__ uint4 g_c1[NMAX * 32];    // combined: .x.y = x_k fp16x4, .z.w = s_k fp16x4
__device__ uint4 g_c2[NMAX * 32];
__device__ uint4 g_c3[NMAX * 32];
__device__ uint2 g_s3h[NMAX * 32];   // compact s3 fp16 (for pass4 gather)
__device__ uint2 g_d1h[NMAX * 32];   // fp16 SCT diffs
__device__ uint2 g_d2h[NMAX * 32];
__device__ uint2 g_d3h[NMAX * 32];

__device__ __forceinline__ float* degp() { return (float*)g_zero3; }
__device__ __forceinline__ int*   cntp() { return (int*)(g_zero3 + NMAX); }
__device__ __forceinline__ int*   curp() { return (int*)(g_zero3 + 2 * NMAX); }

// final CSR pointer (scan3 folded into consumers)
__device__ __forceinline__ int fptr(int i, int N) {
    return (i >= N) ? g_ptr[N] : (g_ptr[i] + g_bsum[i >> 9]);
}

// ---------------- helpers ----------------
__device__ __forceinline__ float lrelu(float v) { return v > 0.0f ? v : v * SLOPE; }
__device__ __forceinline__ float rlu(float v)   { return v > 0.0f ? v : 0.0f; }

__device__ __forceinline__ float wsum(float v) {
    #pragma unroll
    for (int o = 16; o > 0; o >>= 1) v += __shfl_xor_sync(0xffffffffu, v, o);
    return v;
}
__device__ __forceinline__ unsigned int pack_h2(float x, float y) {
    __half2 a = __floats2half2_rn(x, y);
    return *(unsigned int*)&a;
}
__device__ __forceinline__ float2 unpack_h2(unsigned int u) {
    __half2 a = *(__half2*)&u;
    return __half22float2(a);
}
__device__ __forceinline__ float4 unpack_h4(uint2 u) {
    float2 fa = unpack_h2(u.x), fb = unpack_h2(u.y);
    return make_float4(fa.x, fa.y, fb.x, fb.y);
}
__device__ __forceinline__ unsigned long long pack2(float x, float y) {
    unsigned long long r;
    asm("mov.b64 %0, {%1, %2};" : "=l"(r) : "f"(x), "f"(y));
    return r;
}
__device__ __forceinline__ unsigned long long dup2(float x) {
    unsigned long long r;
    asm("mov.b64 %0, {%1, %1};" : "=l"(r) : "f"(x));
    return r;
}
__device__ __forceinline__ void fma2(unsigned long long &d, unsigned long long a, unsigned long long b) {
    asm("fma.rn.f32x2 %0, %1, %2, %0;" : "+l"(d) : "l"(a), "l"(b));
}
__device__ __forceinline__ float2 unpack2(unsigned long long v) {
    float2 r;
    asm("mov.b64 {%0, %1}, %2;" : "=f"(r.x), "=f"(r.y) : "l"(v));
    return r;
}

// ---------------- setup ----------------
__global__ void k_deg(const int* __restrict__ row, const int* __restrict__ col,
                      const float* __restrict__ w, int E) {
    int e = blockIdx.x * blockDim.x + threadIdx.x;
    if (e >= E) return;
    atomicAdd(&degp()[col[e]], w[e]);
    atomicAdd(&cntp()[row[e]], 1);
}

__global__ void k_scan1(int N) {
    __shared__ int sd[512];
    int tid = threadIdx.x;
    int i = blockIdx.x * 512 + tid;
    if (i < N) {
        float d = degp()[i];
        g_dg[i]   = rsqrtf(d + 1.0f);
        g_dinv[i] = 1.0f / d;
    }
    int v = (i < N) ? ((cntp()[i] + 3) & ~3) : 0;   // pad each segment to x4
    sd[tid] = v;
    __syncthreads();
    #pragma unroll
    for (int off = 1; off < 512; off <<= 1) {
        int t = (tid >= off) ? sd[tid - off] : 0;
        __syncthreads();
        sd[tid] += t;
        __syncthreads();
    }
    if (i < N) g_ptr[i] = sd[tid] - v;
    if (tid == 511) g_bsum[blockIdx.x] = sd[511];
}

__global__ void k_scan2(int nb, int N) {
    __shared__ int sd[1024];
    int tid = threadIdx.x;
    int v = (tid < nb) ? g_bsum[tid] : 0;
    sd[tid] = v;
    __syncthreads();
    #pragma unroll
    for (int off = 1; off < 1024; off <<= 1) {
        int t = (tid >= off) ? sd[tid - off] : 0;
        __syncthreads();
        sd[tid] += t;
        __syncthreads();
    }
    if (tid < nb) g_bsum[tid] = sd[tid] - v;
    if (tid == nb - 1) g_ptr[N] = sd[tid];
}

// fill pad slots with zero-weight dummy edges
__global__ void k_pad(int N) {
    int i = blockIdx.x * blockDim.x + threadIdx.x;
    if (i >= N) return;
    int c = cntp()[i];
    int s = fptr(i, N) + c, e2 = fptr(i + 1, N);
    uint4 z = make_uint4(0u, 0u, 0u, 0u);
    for (int j = s; j < e2; j++) g_edges[j] = z;
}

__global__ void k_scatter(const int* __restrict__ row, const int* __restrict__ col,
                          const float* __restrict__ w, int E, int N) {
    int e = blockIdx.x * blockDim.x + threadIdx.x;
    if (e >= E) return;
    int r = row[e], c = col[e];
    int pos = fptr(r, N) + atomicAdd(&curp()[r], 1);
    float wv = w[e];
    uint4 v;
    v.x = (unsigned int)c;
    v.y = __float_as_uint(wv * g_dg[c]);
    v.z = __float_as_uint(wv * g_dinv[c]);
    v.w = 0u;
    g_edges[pos] = v;
}

// ---------------- pass 1: fp32 gather of X -> combined c1, edge prefetch ----------------
__global__ __launch_bounds__(64, 12)
void k_pass1(const float4* __restrict__ X, int N) {
    int gt = blockIdx.x * 64 + threadIdx.x;
    int wid = gt >> 5, lane = gt & 31;
    if (wid >= N) return;
    int s = fptr(wid, N), e = fptr(wid + 1, N);
    float4 aG = make_float4(0.f,0.f,0.f,0.f);
    float4 aS = make_float4(0.f,0.f,0.f,0.f);
    uint4 E0, E1, E2, E3;
    if (s < e) {
        E0 = __ldg(&g_edges[s]);   E1 = __ldg(&g_edges[s+1]);
        E2 = __ldg(&g_edges[s+2]); E3 = __ldg(&g_edges[s+3]);
    }
    for (int j = s; j < e; j += 4) {
        float4 v0 = __ldg(&X[(int)E0.x*32 + lane]);
        float4 v1 = __ldg(&X[(int)E1.x*32 + lane]);
        float4 v2 = __ldg(&X[(int)E2.x*32 + lane]);
        float4 v3 = __ldg(&X[(int)E3.x*32 + lane]);
        uint4 P0 = __ldg(&g_edges[j+4]), P1 = __ldg(&g_edges[j+5]);
        uint4 P2 = __ldg(&g_edges[j+6]), P3 = __ldg(&g_edges[j+7]);
        float g0 = __uint_as_float(E0.y), g1 = __uint_as_float(E1.y);
        float g2 = __uint_as_float(E2.y), g3 = __uint_as_float(E3.y);
        float q0 = __uint_as_float(E0.z), q1 = __uint_as_float(E1.z);
        float q2 = __uint_as_float(E2.z), q3 = __uint_as_float(E3.z);
        aG.x += g0*v0.x + g1*v1.x + g2*v2.x + g3*v3.x;
        aG.y += g0*v0.y + g1*v1.y + g2*v2.y + g3*v3.y;
        aG.z += g0*v0.z + g1*v1.z + g2*v2.z + g3*v3.z;
        aG.w += g0*v0.w + g1*v1.w + g2*v2.w + g3*v3.w;
        aS.x += q0*v0.x + q1*v1.x + q2*v2.x + q3*v3.x;
        aS.y += q0*v0.y + q1*v1.y + q2*v2.y + q3*v3.y;
        aS.z += q0*v0.z + q1*v1.z + q2*v2.z + q3*v3.z;
        aS.w += q0*v0.w + q1*v1.w + q2*v2.w + q3*v3.w;
        E0 = P0; E1 = P1; E2 = P2; E3 = P3;
    }
    float dg = g_dg[wid];
    float4 xs = X[wid*32 + lane];
    uint4 c;
    c.x = pack_h2((aG.x + xs.x*dg)*dg, (aG.y + xs.y*dg)*dg);
    c.y = pack_h2((aG.z + xs.z*dg)*dg, (aG.w + xs.w*dg)*dg);
    c.z = pack_h2(0.5f*(xs.x + aS.x), 0.5f*(xs.y + aS.y));
    c.w = pack_h2(0.5f*(xs.z + aS.z), 0.5f*(xs.w + aS.w));
    g_c1[wid*32 + lane] = c;
}

// ---------------- mid pass: combined gather -> next combined + diff, edge prefetch ----------------
__global__ __launch_bounds__(64, 12)
void k_pass_mid(const uint4* __restrict__ cin, uint4* __restrict__ cout,
                uint2* __restrict__ dout, uint2* __restrict__ sout, int N) {
    int gt = blockIdx.x * 64 + threadIdx.x;
    int wid = gt >> 5, lane = gt & 31;
    if (wid >= N) return;
    int s = fptr(wid, N), e = fptr(wid + 1, N);
    float4 aG = make_float4(0.f,0.f,0.f,0.f);
    float4 aS = make_float4(0.f,0.f,0.f,0.f);
    uint4 E0, E1, E2, E3;
    if (s < e) {
        E0 = __ldg(&g_edges[s]);   E1 = __ldg(&g_edges[s+1]);
        E2 = __ldg(&g_edges[s+2]); E3 = __ldg(&g_edges[s+3]);
    }
    for (int j = s; j < e; j += 4) {
        uint4 u0 = __ldg(&cin[(int)E0.x*32 + lane]);
        uint4 u1 = __ldg(&cin[(int)E1.x*32 + lane]);
        uint4 u2 = __ldg(&cin[(int)E2.x*32 + lane]);
        uint4 u3 = __ldg(&cin[(int)E3.x*32 + lane]);
        uint4 P0 = __ldg(&g_edges[j+4]), P1 = __ldg(&g_edges[j+5]);
        uint4 P2 = __ldg(&g_edges[j+6]), P3 = __ldg(&g_edges[j+7]);
        float g0 = __uint_as_float(E0.y), g1 = __uint_as_float(E1.y);
        float g2 = __uint_as_float(E2.y), g3 = __uint_as_float(E3.y);
        float q0 = __uint_as_float(E0.z), q1 = __uint_as_float(E1.z);
        float q2 = __uint_as_float(E2.z), q3 = __uint_as_float(E3.z);
        float2 x0a = unpack_h2(u0.x), x0b = unpack_h2(u0.y), s0a = unpack_h2(u0.z), s0b = unpack_h2(u0.w);
        float2 x1a = unpack_h2(u1.x), x1b = unpack_h2(u1.y), s1a = unpack_h2(u1.z), s1b = unpack_h2(u1.w);
        float2 x2a = unpack_h2(u2.x), x2b = unpack_h2(u2.y), s2a = unpack_h2(u2.z), s2b = unpack_h2(u2.w);
        float2 x3a = unpack_h2(u3.x), x3b = unpack_h2(u3.y), s3a = unpack_h2(u3.z), s3b = unpack_h2(u3.w);
        aG.x += g0*x0a.x + g1*x1a.x + g2*x2a.x + g3*x3a.x;
        aG.y += g0*x0a.y + g1*x1a.y + g2*x2a.y + g3*x3a.y;
        aG.z += g0*x0b.x + g1*x1b.x + g2*x2b.x + g3*x3b.x;
        aG.w += g0*x0b.y + g1*x1b.y + g2*x2b.y + g3*x3b.y;
        aS.x += q0*s0a.x + q1*s1a.x + q2*s2a.x + q3*s3a.x;
        aS.y += q0*s0a.y + q1*s1a.y + q2*s2a.y + q3*s3a.y;
        aS.z += q0*s0b.x + q1*s1b.x + q2*s2b.x + q3*s3b.x;
        aS.w += q0*s0b.y + q1*s1b.y + q2*s2b.y + q3*s3b.y;
        E0 = P0; E1 = P1; E2 = P2; E3 = P3;
    }
    float dg = g_dg[wid];
    uint4 cs = cin[wid*32 + lane];
    float2 xga = unpack_h2(cs.x), xgb = unpack_h2(cs.y);
    float2 ssa = unpack_h2(cs.z), ssb = unpack_h2(cs.w);
    uint4 c;
    c.x = pack_h2((aG.x + xga.x*dg)*dg, (aG.y + xga.y*dg)*dg);
    c.y = pack_h2((aG.z + xgb.x*dg)*dg, (aG.w + xgb.y*dg)*dg);
    c.z = pack_h2(0.5f*(ssa.x + aS.x), 0.5f*(ssa.y + aS.y));
    c.w = pack_h2(0.5f*(ssb.x + aS.z), 0.5f*(ssb.y + aS.w));
    uint2 d;
    d.x = pack_h2(0.5f*(ssa.x - aS.x), 0.5f*(ssa.y - aS.y));   // s_k - s_{k+1}
    d.y = pack_h2(0.5f*(ssb.x - aS.z), 0.5f*(ssb.y - aS.w));
    int base = wid*32 + lane;
    cout[base] = c;
    dout[base] = d;
    if (sout) { uint2 sc; sc.x = c.z; sc.y = c.w; sout[base] = sc; }
}

// ---------------- final pass: gather compact s3 (8B/lane) -> d3, edge prefetch ----------------
__global__ __launch_bounds__(64, 12)
void k_pass4(const uint2* __restrict__ sh, uint2* __restrict__ dout, int N) {
    int gt = blockIdx.x * 64 + threadIdx.x;
    int wid = gt >> 5, lane = gt & 31;
    if (wid >= N) return;
    int s = fptr(wid, N), e = fptr(wid + 1, N);
    float4 aS = make_float4(0.f,0.f,0.f,0.f);
    uint4 E0, E1, E2, E3;
    if (s < e) {
        E0 = __ldg(&g_edges[s]);   E1 = __ldg(&g_edges[s+1]);
        E2 = __ldg(&g_edges[s+2]); E3 = __ldg(&g_edges[s+3]);
    }
    for (int j = s; j < e; j += 4) {
        uint2 u0 = __ldg(&sh[(int)E0.x*32 + lane]);
        uint2 u1 = __ldg(&sh[(int)E1.x*32 + lane]);
        uint2 u2 = __ldg(&sh[(int)E2.x*32 + lane]);
        uint2 u3 = __ldg(&sh[(int)E3.x*32 + lane]);
        uint4 P0 = __ldg(&g_edges[j+4]), P1 = __ldg(&g_edges[j+5]);
        uint4 P2 = __ldg(&g_edges[j+6]), P3 = __ldg(&g_edges[j+7]);
        float q0 = __uint_as_float(E0.z), q1 = __uint_as_float(E1.z);
        float q2 = __uint_as_float(E2.z), q3 = __uint_as_float(E3.z);
        float2 s0a = unpack_h2(u0.x), s0b = unpack_h2(u0.y);
        float2 s1a = unpack_h2(u1.x), s1b = unpack_h2(u1.y);
        float2 s2a = unpack_h2(u2.x), s2b = unpack_h2(u2.y);
        float2 s3a = unpack_h2(u3.x), s3b = unpack_h2(u3.y);
        aS.x += q0*s0a.x + q1*s1a.x + q2*s2a.x + q3*s3a.x;
        aS.y += q0*s0a.y + q1*s1a.y + q2*s2a.y + q3*s3a.y;
        aS.z += q0*s0b.x + q1*s1b.x + q2*s2b.x + q3*s3b.x;
        aS.w += q0*s0b.y + q1*s1b.y + q2*s2b.y + q3*s3b.y;
        E0 = P0; E1 = P1; E2 = P2; E3 = P3;
    }
    uint2 cs = sh[wid*32 + lane];
    float2 ssa = unpack_h2(cs.x), ssb = unpack_h2(cs.y);
    uint2 d;
    d.x = pack_h2(0.5f*(ssa.x - aS.x), 0.5f*(ssa.y - aS.y));
    d.y = pack_h2(0.5f*(ssb.x - aS.z), 0.5f*(ssb.y - aS.w));
    dout[wid*32 + lane] = d;
}

// ---------------- fused epilogue: attention + GEMM1 + GEMM2 ----------------
__device__ __forceinline__ float4 lrelu4(float4 v) {
    return make_float4(lrelu(v.x), lrelu(v.y), lrelu(v.z), lrelu(v.w));
}
__device__ __forceinline__ float apw(float d, bool is1, float mf) {
    float a = fabsf(d);
    return is1 ? a : __powf(a, mf);
}

__device__ __forceinline__ void wtrans(const float* __restrict__ W, float* Wt,
                                       float stage[32][33], int tid) {
    int tx = tid & 31, ty0 = tid >> 5;
    for (int t = 0; t < 16; t++) {
        int ko = (t >> 2) << 5, oo = (t & 3) << 5;
        #pragma unroll
        for (int i = 0; i < 4; i++) {
            int ty = ty0 + i * 8;
            stage[ty][tx] = W[(oo + ty) * D + ko + tx];
        }
        __syncthreads();
        #pragma unroll
        for (int i = 0; i < 4; i++) {
            int ty = ty0 + i * 8;
            Wt[(ko + ty) * D + oo + tx] = stage[tx][ty];
        }
        __syncthreads();
    }
}

__device__ __forceinline__ void gemm_core(const float* hs, const float* Wt,
                                          int wid, int lane, unsigned long long acc[16][2]) {
    int o4 = lane << 2;
    #pragma unroll
    for (int r = 0; r < 16; r++) { acc[r][0] = 0ull; acc[r][1] = 0ull; }
    for (int k4 = 0; k4 < 32; k4++) {
        unsigned long long wp[4][2];
        #pragma unroll
        for (int kk = 0; kk < 4; kk++) {
            float4 wv = *(const float4*)&Wt[(k4 * 4 + kk) * D + o4];
            wp[kk][0] = pack2(wv.x, wv.y);
            wp[kk][1] = pack2(wv.z, wv.w);
        }
        #pragma unroll
        for (int r = 0; r < 16; r++) {
            float4 h4 = *(const float4*)&hs[(wid * 16 + r) * D + k4 * 4];
            unsigned long long hp;
            hp = dup2(h4.x); fma2(acc[r][0], hp, wp[0][0]); fma2(acc[r][1], hp, wp[0][1]);
            hp = dup2(h4.y); fma2(acc[r][0], hp, wp[1][0]); fma2(acc[r][1], hp, wp[1][1]);
            hp = dup2(h4.z); fma2(acc[r][0], hp, wp[2][0]); fma2(acc[r][1], hp, wp[2][1]);
            hp = dup2(h4.w); fma2(acc[r][0], hp, wp[3][0]); fma2(acc[r][1], hp, wp[3][1]);
        }
    }
}

extern __shared__ float dsm[];
__global__ __launch_bounds__(256, 1)
void k_epilogue(const float4* __restrict__ X, const float4* __restrict__ a4,
                const int* __restrict__ mom,
                const float* __restrict__ W1, const float* __restrict__ b1,
                const float* __restrict__ W2, const float* __restrict__ b2,
                float* __restrict__ out, int N) {
    float* Wt = dsm;
    float* hs = dsm + 16384;
    __shared__ float stage[32][33];

    int tid = threadIdx.x, wid = tid >> 5, lane = tid & 31;
    int row0 = blockIdx.x * 128;
    float4* hs4 = (float4*)hs;

    float4 aX = a4[lane];
    float4 aH = a4[32 + lane];
    int mi = mom[0];
    bool is1 = (mi == 1) || (__int_as_float(mi) == 1.0f);
    float mf = 1.0f;
    if (!is1) mf = (mi > 0 && mi < 64) ? (float)mi : __int_as_float(mi);

    // Phase A: attention -> hs
    for (int r = 0; r < 16; r++) {
        int n = row0 + wid * 16 + r;
        float4 o = make_float4(0.f, 0.f, 0.f, 0.f);
        if (n < N) {
            int base = n * 32 + lane;
            float4 xr = X[base];
            float eX = wsum(rlu(xr.x)*aX.x + rlu(xr.y)*aX.y + rlu(xr.z)*aX.z + rlu(xr.w)*aX.w);

            uint4 c1 = g_c1[base], c2 = g_c2[base], c3 = g_c3[base];
            float4 h[6];
            h[0] = lrelu4(unpack_h4(make_uint2(c1.x, c1.y)));
            h[1] = lrelu4(unpack_h4(make_uint2(c2.x, c2.y)));
            h[2] = lrelu4(unpack_h4(make_uint2(c3.x, c3.y)));
            float4 d1 = unpack_h4(g_d1h[base]);
            float4 d2 = unpack_h4(g_d2h[base]);
            float4 d3 = unpack_h4(g_d3h[base]);
            h[3] = make_float4(apw(d1.x,is1,mf), apw(d1.y,is1,mf), apw(d1.z,is1,mf), apw(d1.w,is1,mf));
            h[4] = make_float4(apw(d2.x,is1,mf), apw(d2.y,is1,mf), apw(d2.z,is1,mf), apw(d2.w,is1,mf));
            h[5] = make_float4(apw(d3.x,is1,mf), apw(d3.y,is1,mf), apw(d3.z,is1,mf), apw(d3.w,is1,mf));

            float e[6];
            #pragma unroll
            for (int c = 0; c < 6; c++) {
                float part = rlu(h[c].x)*aH.x + rlu(h[c].y)*aH.y + rlu(h[c].z)*aH.z + rlu(h[c].w)*aH.w;
                e[c] = eX + wsum(part);
            }
            float mx = e[0];
            #pragma unroll
            for (int c = 1; c < 6; c++) mx = fmaxf(mx, e[c]);
            float at[6], s = 0.f;
            #pragma unroll
            for (int c = 0; c < 6; c++) { at[c] = __expf(e[c] - mx); s += at[c]; }
            float inv = 1.0f / (6.0f * s);
            #pragma unroll
            for (int c = 0; c < 6; c++) {
                o.x += at[c]*h[c].x; o.y += at[c]*h[c].y; o.z += at[c]*h[c].z; o.w += at[c]*h[c].w;
            }
            o.x *= inv; o.y *= inv; o.z *= inv; o.w *= inv;
        }
        hs4[(wid * 16 + r) * 32 + lane] = o;
    }
    __syncthreads();

    // Phase B: GEMM1 -> hs in place
    wtrans(W1, Wt, stage, tid);
    unsigned long long acc[16][2];
    gemm_core(hs, Wt, wid, lane, acc);
    __syncthreads();
    {
        int o4 = lane << 2;
        float4 bb = *(const float4*)&b1[o4];
        #pragma unroll
        for (int r = 0; r < 16; r++) {
            float2 lo = unpack2(acc[r][0]);
            float2 hi = unpack2(acc[r][1]);
            float4 o;
            o.x = lrelu(lo.x + bb.x);
            o.y = lrelu(lo.y + bb.y);
            o.z = lrelu(hi.x + bb.z);
            o.w = lrelu(hi.y + bb.w);
            *(float4*)&hs[(wid * 16 + r) * D + o4] = o;
        }
    }
    __syncthreads();

    // Phase C: GEMM2 -> gmem
    wtrans(W2, Wt, stage, tid);
    gemm_core(hs, Wt, wid, lane, acc);
    {
        int o4 = lane << 2;
        float4 bb = *(const float4*)&b2[o4];
        #pragma unroll
        for (int r = 0; r < 16; r++) {
            int rr = row0 + wid * 16 + r;
            if (rr < N) {
                float2 lo = unpack2(acc[r][0]);
                float2 hi = unpack2(acc[r][1]);
                float4 o;
                o.x = lrelu(lo.x + bb.x);
                o.y = lrelu(lo.y + bb.y);
                o.z = lrelu(hi.x + bb.z);
                o.w = lrelu(hi.y + bb.w);
                *(float4*)&out[(size_t)rr * D + o4] = o;
            }
        }
    }
}

// ---------------- launch ----------------
extern "C" void kernel_launch(void* const* d_in, const int* in_sizes, int n_in,
                              void* d_out, int out_size) {
    const float* X   = (const float*)d_in[0];
    const int*   ei  = (const int*)d_in[1];
    const float* ew  = (const float*)d_in[2];
    const float* W1  = (const float*)d_in[3];
    const float* b1  = (const float*)d_in[4];
    const float* W2  = (const float*)d_in[5];
    const float* b2  = (const float*)d_in[6];
    const float* av  = (const float*)d_in[7];
    const int*   mom = (const int*)d_in[8];

    int N = in_sizes[0] / D;
    int E = in_sizes[2];
    const int* row = ei;
    const int* col = ei + E;

    void *p_zero, *p_c1, *p_c2, *p_c3, *p_s3h, *p_d1h, *p_d2h, *p_d3h;
    cudaGetSymbolAddress(&p_zero, g_zero3);
    cudaGetSymbolAddress(&p_c1, g_c1);
    cudaGetSymbolAddress(&p_c2, g_c2);
    cudaGetSymbolAddress(&p_c3, g_c3);
    cudaGetSymbolAddress(&p_s3h, g_s3h);
    cudaGetSymbolAddress(&p_d1h, g_d1h);
    cudaGetSymbolAddress(&p_d2h, g_d2h);
    cudaGetSymbolAddress(&p_d3h, g_d3h);

    cudaMemsetAsync(p_zero, 0, 3 * NMAX * sizeof(unsigned int), 0);

    int eb = (E + 255) / 256;
    int nb = (N + 255) / 256;
    int wb64 = (N * 32 + 63) / 64;
    int sb = (N + 511) / 512;

    k_deg<<<eb, 256>>>(row, col, ew, E);
    k_scan1<<<sb, 512>>>(N);
    k_scan2<<<1, 1024>>>(sb, N);
    k_pad<<<nb, 256>>>(N);
    k_scatter<<<eb, 256>>>(row, col, ew, E, N);

    k_pass1<<<wb64, 64>>>((const float4*)X, N);
    k_pass_mid<<<wb64, 64>>>((const uint4*)p_c1, (uint4*)p_c2, (uint2*)p_d1h, (uint2*)0, N);
    k_pass_mid<<<wb64, 64>>>((const uint4*)p_c2, (uint4*)p_c3, (uint2*)p_d2h, (uint2*)p_s3h, N);
    k_pass4<<<wb64, 64>>>((const uint2*)p_s3h, (uint2*)p_d3h, N);

    cudaFuncSetAttribute(k_epilogue, cudaFuncAttributeMaxDynamicSharedMemorySize, 131072);
    int gb = (N + 127) / 128;
    k_epilogue<<<gb, 256, 131072>>>((const float4*)X, (const float4*)av, mom,
                                    W1, b1, W2, b2, (float*)d_out, N);
}

// round 7
// speedup vs baseline: 1.0268x; 1.0268x over previous
#include <cuda_runtime.h>
#include <cuda_bf16.h>
#include <cuda_fp16.h>
#include <math.h>

#define D 128
#define NMAX 50048
#define EMAX 960000
#define SLOPE 0.01f

// ---------------- static device scratch ----------------
// zeroed-per-launch region: [0,NMAX)=deg(f32), [NMAX,2N)=cnt(i32), [2N,3N)=cur(i32)
__device__ unsigned int g_zero3[3 * NMAX];
__device__ float g_dg[NMAX];
__device__ float g_dinv[NMAX];
__device__ int   g_ptr[NMAX + 1];
__device__ int   g_bsum[1024];
__device__ uint4 g_edges[EMAX];      // {col, wG, wS, pad}
__device__ uint2 g_xh [NMAX * 32];   // X as fp16 (4 feats / 8B per lane)
__device__ uint2 g_cx1[NMAX * 32];   // GCN chain fp16
__device__ uint2 g_cx2[NMAX * 32];
__device__ uint2 g_cx3[NMAX * 32];
__device__ uint2 g_cs1[NMAX * 32];   // SCT chain fp16
__device__ uint2 g_cs2[NMAX * 32];
__device__ uint2 g_cs3[NMAX * 32];
__device__ uint2 g_d1h[NMAX * 32];   // fp16 SCT diffs
__device__ uint2 g_d2h[NMAX * 32];
__device__ uint2 g_d3h[NMAX * 32];

__device__ __forceinline__ float* degp() { return (float*)g_zero3; }
__device__ __forceinline__ int*   cntp() { return (int*)(g_zero3 + NMAX); }
__device__ __forceinline__ int*   curp() { return (int*)(g_zero3 + 2 * NMAX); }

// final CSR pointer (scan3 folded into consumers)
__device__ __forceinline__ int fptr(int i, int N) {
    return (i >= N) ? g_ptr[N] : (g_ptr[i] + g_bsum[i >> 9]);
}

// ---------------- helpers ----------------
__device__ __forceinline__ float lrelu(float v) { return v > 0.0f ? v : v * SLOPE; }
__device__ __forceinline__ float rlu(float v)   { return v > 0.0f ? v : 0.0f; }

__device__ __forceinline__ float wsum(float v) {
    #pragma unroll
    for (int o = 16; o > 0; o >>= 1) v += __shfl_xor_sync(0xffffffffu, v, o);
    return v;
}
__device__ __forceinline__ unsigned int pack_h2(float x, float y) {
    __half2 a = __floats2half2_rn(x, y);
    return *(unsigned int*)&a;
}
__device__ __forceinline__ float2 unpack_h2(unsigned int u) {
    __half2 a = *(__half2*)&u;
    return __half22float2(a);
}
__device__ __forceinline__ uint2 pack_h4(float4 v) {
    uint2 r;
    r.x = pack_h2(v.x, v.y);
    r.y = pack_h2(v.z, v.w);
    return r;
}
__device__ __forceinline__ float4 unpack_h4(uint2 u) {
    float2 fa = unpack_h2(u.x), fb = unpack_h2(u.y);
    return make_float4(fa.x, fa.y, fb.x, fb.y);
}
__device__ __forceinline__ unsigned long long pack2(float x, float y) {
    unsigned long long r;
    asm("mov.b64 %0, {%1, %2};" : "=l"(r) : "f"(x), "f"(y));
    return r;
}
__device__ __forceinline__ unsigned long long dup2(float x) {
    unsigned long long r;
    asm("mov.b64 %0, {%1, %1};" : "=l"(r) : "f"(x));
    return r;
}
__device__ __forceinline__ void fma2(unsigned long long &d, unsigned long long a, unsigned long long b) {
    asm("fma.rn.f32x2 %0, %1, %2, %0;" : "+l"(d) : "l"(a), "l"(b));
}
__device__ __forceinline__ float2 unpack2(unsigned long long v) {
    float2 r;
    asm("mov.b64 {%0, %1}, %2;" : "=f"(r.x), "=f"(r.y) : "l"(v));
    return r;
}

// ---------------- setup ----------------
__global__ void k_deg(const int* __restrict__ row, const int* __restrict__ col,
                      const float* __restrict__ w, int E) {
    int e = blockIdx.x * blockDim.x + threadIdx.x;
    if (e >= E) return;
    atomicAdd(&degp()[col[e]], w[e]);
    atomicAdd(&cntp()[row[e]], 1);
}

__global__ void k_scan1(int N) {
    __shared__ int sd[512];
    int tid = threadIdx.x;
    int i = blockIdx.x * 512 + tid;
    if (i < N) {
        float d = degp()[i];
        g_dg[i]   = rsqrtf(d + 1.0f);
        g_dinv[i] = 1.0f / d;
    }
    int v = (i < N) ? cntp()[i] : 0;
    sd[tid] = v;
    __syncthreads();
    #pragma unroll
    for (int off = 1; off < 512; off <<= 1) {
        int t = (tid >= off) ? sd[tid - off] : 0;
        __syncthreads();
        sd[tid] += t;
        __syncthreads();
    }
    if (i < N) g_ptr[i] = sd[tid] - v;
    if (tid == 511) g_bsum[blockIdx.x] = sd[511];
}

__global__ void k_scan2(int nb, int N) {
    __shared__ int sd[1024];
    int tid = threadIdx.x;
    int v = (tid < nb) ? g_bsum[tid] : 0;
    sd[tid] = v;
    __syncthreads();
    #pragma unroll
    for (int off = 1; off < 1024; off <<= 1) {
        int t = (tid >= off) ? sd[tid - off] : 0;
        __syncthreads();
        sd[tid] += t;
        __syncthreads();
    }
    if (tid < nb) g_bsum[tid] = sd[tid] - v;
    if (tid == nb - 1) g_ptr[N] = sd[tid];
}

__global__ void k_scatter(const int* __restrict__ row, const int* __restrict__ col,
                          const float* __restrict__ w, int E, int N) {
    int e = blockIdx.x * blockDim.x + threadIdx.x;
    if (e >= E) return;
    int r = row[e], c = col[e];
    int pos = fptr(r, N) + atomicAdd(&curp()[r], 1);
    float wv = w[e];
    uint4 v;
    v.x = (unsigned int)c;
    v.y = __float_as_uint(wv * g_dg[c]);
    v.z = __float_as_uint(wv * g_dinv[c]);
    v.w = 0u;
    g_edges[pos] = v;
}

// ---------------- X -> fp16 conversion (streaming) ----------------
__global__ void k_xh(const float4* __restrict__ X, int NL) {
    int i = blockIdx.x * 256 + threadIdx.x;
    if (i < NL) g_xh[i] = pack_h4(X[i]);
}

// ---------------- pass 1: one warp per node, gathers fp16 X, both chains ----------------
__global__ __launch_bounds__(64, 16)
void k_pass1(const float4* __restrict__ X, int N) {
    int gt = blockIdx.x * 64 + threadIdx.x;
    int wid = gt >> 5, lane = gt & 31;
    if (wid >= N) return;
    int s = fptr(wid, N), e = fptr(wid + 1, N);
    float4 aG = make_float4(0.f,0.f,0.f,0.f);
    float4 aS = make_float4(0.f,0.f,0.f,0.f);
    int j = s;
    for (; j + 4 <= e; j += 4) {
        uint4 e0 = __ldg(&g_edges[j]),   e1 = __ldg(&g_edges[j+1]);
        uint4 e2 = __ldg(&g_edges[j+2]), e3 = __ldg(&g_edges[j+3]);
        uint2 u0 = __ldg(&g_xh[(int)e0.x*32 + lane]);
        uint2 u1 = __ldg(&g_xh[(int)e1.x*32 + lane]);
        uint2 u2 = __ldg(&g_xh[(int)e2.x*32 + lane]);
        uint2 u3 = __ldg(&g_xh[(int)e3.x*32 + lane]);
        float g0 = __uint_as_float(e0.y), g1 = __uint_as_float(e1.y);
        float g2 = __uint_as_float(e2.y), g3 = __uint_as_float(e3.y);
        float q0 = __uint_as_float(e0.z), q1 = __uint_as_float(e1.z);
        float q2 = __uint_as_float(e2.z), q3 = __uint_as_float(e3.z);
        float4 v0 = unpack_h4(u0), v1 = unpack_h4(u1);
        float4 v2 = unpack_h4(u2), v3 = unpack_h4(u3);
        aG.x += g0*v0.x + g1*v1.x + g2*v2.x + g3*v3.x;
        aG.y += g0*v0.y + g1*v1.y + g2*v2.y + g3*v3.y;
        aG.z += g0*v0.z + g1*v1.z + g2*v2.z + g3*v3.z;
        aG.w += g0*v0.w + g1*v1.w + g2*v2.w + g3*v3.w;
        aS.x += q0*v0.x + q1*v1.x + q2*v2.x + q3*v3.x;
        aS.y += q0*v0.y + q1*v1.y + q2*v2.y + q3*v3.y;
        aS.z += q0*v0.z + q1*v1.z + q2*v2.z + q3*v3.z;
        aS.w += q0*v0.w + q1*v1.w + q2*v2.w + q3*v3.w;
    }
    for (; j < e; j++) {
        uint4 ev = __ldg(&g_edges[j]);
        float4 v = unpack_h4(__ldg(&g_xh[(int)ev.x*32 + lane]));
        float gw = __uint_as_float(ev.y), qw = __uint_as_float(ev.z);
        aG.x += gw*v.x; aG.y += gw*v.y; aG.z += gw*v.z; aG.w += gw*v.w;
        aS.x += qw*v.x; aS.y += qw*v.y; aS.z += qw*v.z; aS.w += qw*v.w;
    }
    float dg = g_dg[wid];
    float4 xs = X[wid*32 + lane];   // self term in fp32
    int base = wid*32 + lane;
    uint2 cx, cs;
    cx.x = pack_h2((aG.x + xs.x*dg)*dg, (aG.y + xs.y*dg)*dg);
    cx.y = pack_h2((aG.z + xs.z*dg)*dg, (aG.w + xs.w*dg)*dg);
    cs.x = pack_h2(0.5f*(xs.x + aS.x), 0.5f*(xs.y + aS.y));
    cs.y = pack_h2(0.5f*(xs.z + aS.z), 0.5f*(xs.w + aS.w));
    g_cx1[base] = cx;
    g_cs1[base] = cs;
}

// ---------------- mid pass: 2 warps per node; warp0 = GCN chain, warp1 = SCT chain ----------------
__global__ __launch_bounds__(64, 16)
void k_mid(const uint2* __restrict__ xin, const uint2* __restrict__ sin_,
           uint2* __restrict__ xout, uint2* __restrict__ sout,
           uint2* __restrict__ dout, int N) {
    int node = blockIdx.x;
    if (node >= N) return;
    int lane = threadIdx.x & 31;
    int s = fptr(node, N), e = fptr(node + 1, N);
    int base = node*32 + lane;

    if ((threadIdx.x >> 5) == 0) {
        // GCN chain: gather xin with wG
        float4 a = make_float4(0.f,0.f,0.f,0.f);
        int j = s;
        for (; j + 4 <= e; j += 4) {
            uint4 e0 = __ldg(&g_edges[j]),   e1 = __ldg(&g_edges[j+1]);
            uint4 e2 = __ldg(&g_edges[j+2]), e3 = __ldg(&g_edges[j+3]);
            uint2 u0 = __ldg(&xin[(int)e0.x*32 + lane]);
            uint2 u1 = __ldg(&xin[(int)e1.x*32 + lane]);
            uint2 u2 = __ldg(&xin[(int)e2.x*32 + lane]);
            uint2 u3 = __ldg(&xin[(int)e3.x*32 + lane]);
            float g0 = __uint_as_float(e0.y), g1 = __uint_as_float(e1.y);
            float g2 = __uint_as_float(e2.y), g3 = __uint_as_float(e3.y);
            float4 v0 = unpack_h4(u0), v1 = unpack_h4(u1);
            float4 v2 = unpack_h4(u2), v3 = unpack_h4(u3);
            a.x += g0*v0.x + g1*v1.x + g2*v2.x + g3*v3.x;
            a.y += g0*v0.y + g1*v1.y + g2*v2.y + g3*v3.y;
            a.z += g0*v0.z + g1*v1.z + g2*v2.z + g3*v3.z;
            a.w += g0*v0.w + g1*v1.w + g2*v2.w + g3*v3.w;
        }
        for (; j < e; j++) {
            uint4 ev = __ldg(&g_edges[j]);
            float4 v = unpack_h4(__ldg(&xin[(int)ev.x*32 + lane]));
            float gw = __uint_as_float(ev.y);
            a.x += gw*v.x; a.y += gw*v.y; a.z += gw*v.z; a.w += gw*v.w;
        }
        float dg = g_dg[node];
        float4 xg = unpack_h4(xin[base]);
        uint2 cx;
        cx.x = pack_h2((a.x + xg.x*dg)*dg, (a.y + xg.y*dg)*dg);
        cx.y = pack_h2((a.z + xg.z*dg)*dg, (a.w + xg.w*dg)*dg);
        xout[base] = cx;
    } else {
        // SCT chain: gather sin_ with wS
        float4 a = make_float4(0.f,0.f,0.f,0.f);
        int j = s;
        for (; j + 4 <= e; j += 4) {
            uint4 e0 = __ldg(&g_edges[j]),   e1 = __ldg(&g_edges[j+1]);
            uint4 e2 = __ldg(&g_edges[j+2]), e3 = __ldg(&g_edges[j+3]);
            uint2 u0 = __ldg(&sin_[(int)e0.x*32 + lane]);
            uint2 u1 = __ldg(&sin_[(int)e1.x*32 + lane]);
            uint2 u2 = __ldg(&sin_[(int)e2.x*32 + lane]);
            uint2 u3 = __ldg(&sin_[(int)e3.x*32 + lane]);
            float q0 = __uint_as_float(e0.z), q1 = __uint_as_float(e1.z);
            float q2 = __uint_as_float(e2.z), q3 = __uint_as_float(e3.z);
            float4 v0 = unpack_h4(u0), v1 = unpack_h4(u1);
            float4 v2 = unpack_h4(u2), v3 = unpack_h4(u3);
            a.x += q0*v0.x + q1*v1.x + q2*v2.x + q3*v3.x;
            a.y += q0*v0.y + q1*v1.y + q2*v2.y + q3*v3.y;
            a.z += q0*v0.z + q1*v1.z + q2*v2.z + q3*v3.z;
            a.w += q0*v0.w + q1*v1.w + q2*v2.w + q3*v3.w;
        }
        for (; j < e; j++) {
            uint4 ev = __ldg(&g_edges[j]);
            float4 v = unpack_h4(__ldg(&sin_[(int)ev.x*32 + lane]));
            float qw = __uint_as_float(ev.z);
            a.x += qw*v.x; a.y += qw*v.y; a.z += qw*v.z; a.w += qw*v.w;
        }
        float4 ss = unpack_h4(sin_[base]);
        uint2 cs, d;
        cs.x = pack_h2(0.5f*(ss.x + a.x), 0.5f*(ss.y + a.y));
        cs.y = pack_h2(0.5f*(ss.z + a.z), 0.5f*(ss.w + a.w));
        d.x  = pack_h2(0.5f*(ss.x - a.x), 0.5f*(ss.y - a.y));  // s_k - s_{k+1}
        d.y  = pack_h2(0.5f*(ss.z - a.z), 0.5f*(ss.w - a.w));
        sout[base] = cs;
        dout[base] = d;
    }
}

// ---------------- final pass: gather cs3 (8B/lane) -> d3 ----------------
__global__ __launch_bounds__(64, 16)
void k_pass4(const uint2* __restrict__ sh, uint2* __restrict__ dout, int N) {
    int gt = blockIdx.x * 64 + threadIdx.x;
    int wid = gt >> 5, lane = gt & 31;
    if (wid >= N) return;
    int s = fptr(wid, N), e = fptr(wid + 1, N);
    float4 aS = make_float4(0.f,0.f,0.f,0.f);
    int j = s;
    for (; j + 4 <= e; j += 4) {
        uint4 e0 = __ldg(&g_edges[j]),   e1 = __ldg(&g_edges[j+1]);
        uint4 e2 = __ldg(&g_edges[j+2]), e3 = __ldg(&g_edges[j+3]);
        uint2 u0 = __ldg(&sh[(int)e0.x*32 + lane]);
        uint2 u1 = __ldg(&sh[(int)e1.x*32 + lane]);
        uint2 u2 = __ldg(&sh[(int)e2.x*32 + lane]);
        uint2 u3 = __ldg(&sh[(int)e3.x*32 + lane]);
        float q0 = __uint_as_float(e0.z), q1 = __uint_as_float(e1.z);
        float q2 = __uint_as_float(e2.z), q3 = __uint_as_float(e3.z);
        float4 v0 = unpack_h4(u0), v1 = unpack_h4(u1);
        float4 v2 = unpack_h4(u2), v3 = unpack_h4(u3);
        aS.x += q0*v0.x + q1*v1.x + q2*v2.x + q3*v3.x;
        aS.y += q0*v0.y + q1*v1.y + q2*v2.y + q3*v3.y;
        aS.z += q0*v0.z + q1*v1.z + q2*v2.z + q3*v3.z;
        aS.w += q0*v0.w + q1*v1.w + q2*v2.w + q3*v3.w;
    }
    for (; j < e; j++) {
        uint4 ev = __ldg(&g_edges[j]);
        float4 v = unpack_h4(__ldg(&sh[(int)ev.x*32 + lane]));
        float qw = __uint_as_float(ev.z);
        aS.x += qw*v.x; aS.y += qw*v.y; aS.z += qw*v.z; aS.w += qw*v.w;
    }
    float4 ss = unpack_h4(sh[wid*32 + lane]);
    uint2 d;
    d.x = pack_h2(0.5f*(ss.x - aS.x), 0.5f*(ss.y - aS.y));
    d.y = pack_h2(0.5f*(ss.z - aS.z), 0.5f*(ss.w - aS.w));
    dout[wid*32 + lane] = d;
}

// ---------------- fused epilogue: attention + GEMM1 + GEMM2 ----------------
__device__ __forceinline__ float4 lrelu4(float4 v) {
    return make_float4(lrelu(v.x), lrelu(v.y), lrelu(v.z), lrelu(v.w));
}
__device__ __forceinline__ float apw(float d, bool is1, float mf) {
    float a = fabsf(d);
    return is1 ? a : __powf(a, mf);
}

__device__ __forceinline__ void wtrans(const float* __restrict__ W, float* Wt,
                                       float stage[32][33], int tid) {
    int tx = tid & 31, ty0 = tid >> 5;
    for (int t = 0; t < 16; t++) {
        int ko = (t >> 2) << 5, oo = (t & 3) << 5;
        #pragma unroll
        for (int i = 0; i < 4; i++) {
            int ty = ty0 + i * 8;
            stage[ty][tx] = W[(oo + ty) * D + ko + tx];
        }
        __syncthreads();
        #pragma unroll
        for (int i = 0; i < 4; i++) {
            int ty = ty0 + i * 8;
            Wt[(ko + ty) * D + oo + tx] = stage[tx][ty];
        }
        __syncthreads();
    }
}

__device__ __forceinline__ void gemm_core(const float* hs, const float* Wt,
                                          int wid, int lane, unsigned long long acc[16][2]) {
    int o4 = lane << 2;
    #pragma unroll
    for (int r = 0; r < 16; r++) { acc[r][0] = 0ull; acc[r][1] = 0ull; }
    for (int k4 = 0; k4 < 32; k4++) {
        unsigned long long wp[4][2];
        #pragma unroll
        for (int kk = 0; kk < 4; kk++) {
            float4 wv = *(const float4*)&Wt[(k4 * 4 + kk) * D + o4];
            wp[kk][0] = pack2(wv.x, wv.y);
            wp[kk][1] = pack2(wv.z, wv.w);
        }
        #pragma unroll
        for (int r = 0; r < 16; r++) {
            float4 h4 = *(const float4*)&hs[(wid * 16 + r) * D + k4 * 4];
            unsigned long long hp;
            hp = dup2(h4.x); fma2(acc[r][0], hp, wp[0][0]); fma2(acc[r][1], hp, wp[0][1]);
            hp = dup2(h4.y); fma2(acc[r][0], hp, wp[1][0]); fma2(acc[r][1], hp, wp[1][1]);
            hp = dup2(h4.z); fma2(acc[r][0], hp, wp[2][0]); fma2(acc[r][1], hp, wp[2][1]);
            hp = dup2(h4.w); fma2(acc[r][0], hp, wp[3][0]); fma2(acc[r][1], hp, wp[3][1]);
        }
    }
}

extern __shared__ float dsm[];
__global__ __launch_bounds__(256, 1)
void k_epilogue(const float4* __restrict__ X, const float4* __restrict__ a4,
                const int* __restrict__ mom,
                const float* __restrict__ W1, const float* __restrict__ b1,
                const float* __restrict__ W2, const float* __restrict__ b2,
                float* __restrict__ out, int N) {
    float* Wt = dsm;
    float* hs = dsm + 16384;
    __shared__ float stage[32][33];

    int tid = threadIdx.x, wid = tid >> 5, lane = tid & 31;
    int row0 = blockIdx.x * 128;
    float4* hs4 = (float4*)hs;

    float4 aX = a4[lane];
    float4 aH = a4[32 + lane];
    int mi = mom[0];
    bool is1 = (mi == 1) || (__int_as_float(mi) == 1.0f);
    float mf = 1.0f;
    if (!is1) mf = (mi > 0 && mi < 64) ? (float)mi : __int_as_float(mi);

    // Phase A: attention -> hs
    for (int r = 0; r < 16; r++) {
        int n = row0 + wid * 16 + r;
        float4 o = make_float4(0.f, 0.f, 0.f, 0.f);
        if (n < N) {
            int base = n * 32 + lane;
            float4 xr = X[base];
            float eX = wsum(rlu(xr.x)*aX.x + rlu(xr.y)*aX.y + rlu(xr.z)*aX.z + rlu(xr.w)*aX.w);

            float4 h[6];
            h[0] = lrelu4(unpack_h4(g_cx1[base]));
            h[1] = lrelu4(unpack_h4(g_cx2[base]));
            h[2] = lrelu4(unpack_h4(g_cx3[base]));
            float4 d1 = unpack_h4(g_d1h[base]);
            float4 d2 = unpack_h4(g_d2h[base]);
            float4 d3 = unpack_h4(g_d3h[base]);
            h[3] = make_float4(apw(d1.x,is1,mf), apw(d1.y,is1,mf), apw(d1.z,is1,mf), apw(d1.w,is1,mf));
            h[4] = make_float4(apw(d2.x,is1,mf), apw(d2.y,is1,mf), apw(d2.z,is1,mf), apw(d2.w,is1,mf));
            h[5] = make_float4(apw(d3.x,is1,mf), apw(d3.y,is1,mf), apw(d3.z,is1,mf), apw(d3.w,is1,mf));

            float e[6];
            #pragma unroll
            for (int c = 0; c < 6; c++) {
                float part = rlu(h[c].x)*aH.x + rlu(h[c].y)*aH.y + rlu(h[c].z)*aH.z + rlu(h[c].w)*aH.w;
                e[c] = eX + wsum(part);
            }
            float mx = e[0];
            #pragma unroll
            for (int c = 1; c < 6; c++) mx = fmaxf(mx, e[c]);
            float at[6], s = 0.f;
            #pragma unroll
            for (int c = 0; c < 6; c++) { at[c] = __expf(e[c] - mx); s += at[c]; }
            float inv = 1.0f / (6.0f * s);
            #pragma unroll
            for (int c = 0; c < 6; c++) {
                o.x += at[c]*h[c].x; o.y += at[c]*h[c].y; o.z += at[c]*h[c].z; o.w += at[c]*h[c].w;
            }
            o.x *= inv; o.y *= inv; o.z *= inv; o.w *= inv;
        }
        hs4[(wid * 16 + r) * 32 + lane] = o;
    }
    __syncthreads();

    // Phase B: GEMM1 -> hs in place
    wtrans(W1, Wt, stage, tid);
    unsigned long long acc[16][2];
    gemm_core(hs, Wt, wid, lane, acc);
    __syncthreads();
    {
        int o4 = lane << 2;
        float4 bb = *(const float4*)&b1[o4];
        #pragma unroll
        for (int r = 0; r < 16; r++) {
            float2 lo = unpack2(acc[r][0]);
            float2 hi = unpack2(acc[r][1]);
            float4 o;
            o.x = lrelu(lo.x + bb.x);
            o.y = lrelu(lo.y + bb.y);
            o.z = lrelu(hi.x + bb.z);
            o.w = lrelu(hi.y + bb.w);
            *(float4*)&hs[(wid * 16 + r) * D + o4] = o;
        }
    }
    __syncthreads();

    // Phase C: GEMM2 -> gmem
    wtrans(W2, Wt, stage, tid);
    gemm_core(hs, Wt, wid, lane, acc);
    {
        int o4 = lane << 2;
        float4 bb = *(const float4*)&b2[o4];
        #pragma unroll
        for (int r = 0; r < 16; r++) {
            int rr = row0 + wid * 16 + r;
            if (rr < N) {
                float2 lo = unpack2(acc[r][0]);
                float2 hi = unpack2(acc[r][1]);
                float4 o;
                o.x = lrelu(lo.x + bb.x);
                o.y = lrelu(lo.y + bb.y);
                o.z = lrelu(hi.x + bb.z);
                o.w = lrelu(hi.y + bb.w);
                *(float4*)&out[(size_t)rr * D + o4] = o;
            }
        }
    }
}

// ---------------- launch ----------------
extern "C" void kernel_launch(void* const* d_in, const int* in_sizes, int n_in,
                              void* d_out, int out_size) {
    const float* X   = (const float*)d_in[0];
    const int*   ei  = (const int*)d_in[1];
    const float* ew  = (const float*)d_in[2];
    const float* W1  = (const float*)d_in[3];
    const float* b1  = (const float*)d_in[4];
    const float* W2  = (const float*)d_in[5];
    const float* b2  = (const float*)d_in[6];
    const float* av  = (const float*)d_in[7];
    const int*   mom = (const int*)d_in[8];

    int N = in_sizes[0] / D;
    int E = in_sizes[2];
    const int* row = ei;
    const int* col = ei + E;

    void *p_zero, *p_cx1, *p_cx2, *p_cx3, *p_cs1, *p_cs2, *p_cs3, *p_d1h, *p_d2h, *p_d3h;
    cudaGetSymbolAddress(&p_zero, g_zero3);
    cudaGetSymbolAddress(&p_cx1, g_cx1);
    cudaGetSymbolAddress(&p_cx2, g_cx2);
    cudaGetSymbolAddress(&p_cx3, g_cx3);
    cudaGetSymbolAddress(&p_cs1, g_cs1);
    cudaGetSymbolAddress(&p_cs2, g_cs2);
    cudaGetSymbolAddress(&p_cs3, g_cs3);
    cudaGetSymbolAddress(&p_d1h, g_d1h);
    cudaGetSymbolAddress(&p_d2h, g_d2h);
    cudaGetSymbolAddress(&p_d3h, g_d3h);

    cudaMemsetAsync(p_zero, 0, 3 * NMAX * sizeof(unsigned int), 0);

    int eb = (E + 255) / 256;
    int wb64 = (N * 32 + 63) / 64;
    int sb = (N + 511) / 512;
    int NL = N * 32;

    k_deg<<<eb, 256>>>(row, col, ew, E);
    k_scan1<<<sb, 512>>>(N);
    k_scan2<<<1, 1024>>>(sb, N);
    k_scatter<<<eb, 256>>>(row, col, ew, E, N);
    k_xh<<<(NL + 255) / 256, 256>>>((const float4*)X, NL);

    k_pass1<<<wb64, 64>>>((const float4*)X, N);
    k_mid<<<N, 64>>>((const uint2*)p_cx1, (const uint2*)p_cs1,
                     (uint2*)p_cx2, (uint2*)p_cs2, (uint2*)p_d1h, N);
    k_mid<<<N, 64>>>((const uint2*)p_cx2, (const uint2*)p_cs2,
                     (uint2*)p_cx3, (uint2*)p_cs3, (uint2*)p_d2h, N);
    k_pass4<<<wb64, 64>>>((const uint2*)p_cs3, (uint2*)p_d3h, N);

    cudaFuncSetAttribute(k_epilogue, cudaFuncAttributeMaxDynamicSharedMemorySize, 131072);
    int gb = (N + 127) / 128;
    k_epilogue<<<gb, 256, 131072>>>((const float4*)X, (const float4*)av, mom,
                                    W1, b1, W2, b2, (float*)d_out, N);
}